// round 8
// baseline (speedup 1.0000x reference)
#include <cuda_runtime.h>
#include <cuda_fp16.h>
#include <cstdint>
#include <cstddef>

// ---------------- SMEM layout (bytes) ----------------
// Q  : [128 rows][256 d] fp16, row stride 512B, 16B-chunk XOR swizzle -> 64KB
// KV : same layout -> 64KB (K operand for S, V operand (trans ldmatrix) for PV)
// P  : [128 rows][128 kv] fp16, row stride 256B, same swizzle -> 32KB
// RS : float[128][2] rowsum partials per d-half warp
#define SM_Q   0
#define SM_KV  65536
#define SM_P   131072
#define SM_RS  163840
#define SMEM_BYTES 164864

// ---------------- helpers ----------------
__device__ __forceinline__ uint32_t smem_u32(const void* p) {
    uint32_t a;
    asm("{ .reg .u64 t; cvta.to.shared.u64 t, %1; cvt.u32.u64 %0, t; }" : "=r"(a) : "l"(p));
    return a;
}
// pack two fp32 -> fp16x2, a in LOW half
__device__ __forceinline__ uint32_t f2h2(float a, float b) {
    uint32_t r;
    asm("cvt.rn.f16x2.f32 %0, %2, %1;" : "=r"(r) : "f"(a), "f"(b));
    return r;
}

#define STS32(addr, v) \
    asm volatile("st.shared.b32 [%0], %1;" :: "r"(addr), "r"(v) : "memory")
#define STS64(addr, v0, v1) \
    asm volatile("st.shared.v2.b32 [%0], {%1, %2};" :: "r"(addr), "r"(v0), "r"(v1) : "memory")

#define LDSM_X4(r0, r1, r2, r3, addr)                                          \
    asm volatile("ldmatrix.sync.aligned.m8n8.x4.shared.b16 {%0,%1,%2,%3}, [%4];" \
        : "=r"(r0), "=r"(r1), "=r"(r2), "=r"(r3) : "r"(addr))
#define LDSM_X4_T(r0, r1, r2, r3, addr)                                        \
    asm volatile("ldmatrix.sync.aligned.m8n8.x4.trans.shared.b16 {%0,%1,%2,%3}, [%4];" \
        : "=r"(r0), "=r"(r1), "=r"(r2), "=r"(r3) : "r"(addr))

// D(f32x4) += A(f16, m16k16) * B(f16, k16n8)
#define MMA(c, a0, a1, a2, a3, b0, b1)                                         \
    asm volatile("mma.sync.aligned.m16n8k16.row.col.f32.f16.f16.f32 "          \
        "{%0,%1,%2,%3},{%4,%5,%6,%7},{%8,%9},{%0,%1,%2,%3};"                   \
        : "+f"((c)[0]), "+f"((c)[1]), "+f"((c)[2]), "+f"((c)[3])               \
        : "r"(a0), "r"(a1), "r"(a2), "r"(a3), "r"(b0), "r"(b1))

// ---------------- kernel ----------------
// grid 512 = 64 batches x 8 q-tiles of 128 rows; block 512 = 16 warps.
// warp w: rg = w>>1 (16 q-rows at m0=16*rg), dh = w&1 (kv-half in S, d-half in O).
__global__ void __launch_bounds__(512, 1)
attn_kernel(const float* __restrict__ q, const float* __restrict__ kv,
            float* __restrict__ out)
{
    extern __shared__ __align__(16) char smem[];
    const uint32_t sb = smem_u32(smem);
    const int tid  = threadIdx.x;
    const int lane = tid & 31, w = tid >> 5;
    const int rg = w >> 1, dh = w & 1;
    const int m0 = rg << 4;
    const int b  = blockIdx.x >> 3;
    const int q0 = (blockIdx.x & 7) << 7;
    const int g = lane >> 2, tig = lane & 3;
    const int lj = lane & 7, sel = lane >> 3;
    const uint32_t swl = (uint32_t)lj << 4;     // swizzle bits for ldmatrix lane rows

    // ldmatrix lane geometry (rows are multiples of 8/16 so (row&7)==lj always):
    // A-type (Q, P): r0=(m0..+7,k0..7) r1=(+8,k0) r2=(m0,k+8) r3=(+8,k+8)
    const int rowA = m0 + lj + ((sel & 1) << 3);
    const uint32_t colselA = (uint32_t)(sel >> 1) << 4;
    // B-type (K, non-trans): r0=(n0..7,k0..7) r1=(n0..7,k+8) r2=(n0+8,k0) r3=(n0+8,k+8)
    const int rowB = lj + ((sel >> 1) << 3);
    const uint32_t colselB = (uint32_t)(sel & 1) << 4;
    // V-type (trans): r0=(kv0..7,d0..7) r1=(kv+8,d0) r2=(kv0,d+8) r3=(kv+8,d+8)
    const int rowV = lj + ((sel & 1) << 3);
    const uint32_t colselV = colselA;

    const uint32_t aQ = sb + SM_Q + (uint32_t)rowA * 512u;
    const uint32_t aP = sb + SM_P + (uint32_t)rowA * 256u;

    // P store bases (C-fragment rows m0+g and m0+8+g)
    const uint32_t gx  = (uint32_t)g << 4;
    const uint32_t pr0 = sb + SM_P + (uint32_t)(m0 + g) * 256u;
    const uint32_t pr1 = pr0 + 2048u;

    // ---- load Q tile (scale 1/16 folded), fp32 -> fp16, swizzled ----
    {
        const float4* gq = reinterpret_cast<const float4*>(q + ((size_t)(b * 1024 + q0)) * 256);
        #pragma unroll
        for (int i = 0; i < 16; i++) {
            int idx = tid + (i << 9);
            float4 v = gq[idx];
            int r = idx >> 6;
            uint32_t c2 = (uint32_t)(idx & 63) << 3;
            uint32_t ad = sb + SM_Q + (uint32_t)r * 512u + (c2 ^ ((uint32_t)(r & 7) << 4));
            STS64(ad, f2h2(v.x * 0.0625f, v.y * 0.0625f), f2h2(v.z * 0.0625f, v.w * 0.0625f));
        }
    }

    float oacc[64];
    #pragma unroll
    for (int i = 0; i < 64; i++) oacc[i] = 0.f;
    float sum0 = 0.f, sum1 = 0.f;

    const float4* gkv = reinterpret_cast<const float4*>(kv + (size_t)b * 262144);

    for (int t = 0; t < 8; t++) {
        __syncthreads();                        // prev PV done reading KV & P
        // ---- load KV tile t (K and V are the same bytes) ----
        #pragma unroll
        for (int i = 0; i < 16; i++) {
            int idx = tid + (i << 9);
            float4 v = gkv[(t << 13) + idx];
            int r = idx >> 6;
            uint32_t c2 = (uint32_t)(idx & 63) << 3;
            uint32_t ad = sb + SM_KV + (uint32_t)r * 512u + (c2 ^ ((uint32_t)(r & 7) << 4));
            STS64(ad, f2h2(v.x, v.y), f2h2(v.z, v.w));
        }
        __syncthreads();

        // ---- S = Qs . K^T for this warp's 64 kv cols; exp -> P smem ----
        #pragma unroll
        for (int hh = 0; hh < 2; hh++) {
            float acc[16];
            #pragma unroll
            for (int i = 0; i < 16; i++) acc[i] = 0.f;
            #pragma unroll
            for (int kk = 0; kk < 16; kk++) {
                uint32_t a0, a1, a2, a3;
                LDSM_X4(a0, a1, a2, a3, aQ + ((((uint32_t)kk << 5) | colselA) ^ swl));
                #pragma unroll
                for (int nn = 0; nn < 2; nn++) {
                    int n0 = (dh << 6) + (hh << 5) + (nn << 4);
                    uint32_t b0, b1, b2, b3;
                    LDSM_X4(b0, b1, b2, b3,
                            sb + SM_KV + (uint32_t)(n0 + rowB) * 512u
                               + ((((uint32_t)kk << 5) | colselB) ^ swl));
                    MMA(&acc[nn * 8 + 0], a0, a1, a2, a3, b0, b1);
                    MMA(&acc[nn * 8 + 4], a0, a1, a2, a3, b2, b3);
                }
            }
            #pragma unroll
            for (int j = 0; j < 4; j++) {
                int nn = j >> 1, tt = j & 1;
                float* c = &acc[nn * 8 + tt * 4];
                float e0 = __expf(c[0]), e1 = __expf(c[1]);
                float e2 = __expf(c[2]), e3 = __expf(c[3]);
                sum0 += e0 + e1;
                sum1 += e2 + e3;
                uint32_t col2 = ((uint32_t)((dh << 6) + (hh << 5) + (nn << 4) + (tt << 3)) << 1)
                              + ((uint32_t)tig << 2);
                STS32(pr0 + (col2 ^ gx), f2h2(e0, e1));
                STS32(pr1 + (col2 ^ gx), f2h2(e2, e3));
            }
        }
        __syncthreads();                        // P halves exchanged between dh pair

        // ---- O += P . V  (this warp's 128-d half) ----
        #pragma unroll
        for (int kk = 0; kk < 8; kk++) {
            uint32_t a0, a1, a2, a3;
            LDSM_X4(a0, a1, a2, a3, aP + ((((uint32_t)kk << 5) | colselA) ^ swl));
            #pragma unroll
            for (int dd = 0; dd < 8; dd++) {
                int d0 = (dh << 7) + (dd << 4);
                uint32_t b0, b1, b2, b3;
                LDSM_X4_T(b0, b1, b2, b3,
                          sb + SM_KV + (uint32_t)((kk << 4) + rowV) * 512u
                             + ((((uint32_t)d0 << 1) | colselV) ^ swl));
                MMA(&oacc[dd * 8 + 0], a0, a1, a2, a3, b0, b1);
                MMA(&oacc[dd * 8 + 4], a0, a1, a2, a3, b2, b3);
            }
        }
    }

    // ---- rowsums: reduce within quad, combine dh halves via smem ----
    sum0 += __shfl_xor_sync(0xffffffffu, sum0, 1);
    sum0 += __shfl_xor_sync(0xffffffffu, sum0, 2);
    sum1 += __shfl_xor_sync(0xffffffffu, sum1, 1);
    sum1 += __shfl_xor_sync(0xffffffffu, sum1, 2);
    float* rs = reinterpret_cast<float*>(smem + SM_RS);
    if (tig == 0) {
        rs[((m0 + g) << 1) + dh]     = sum0;
        rs[((m0 + 8 + g) << 1) + dh] = sum1;
    }
    __syncthreads();
    const float inv0 = 1.0f / (rs[(m0 + g) << 1]     + rs[((m0 + g) << 1) + 1]);
    const float inv1 = 1.0f / (rs[(m0 + 8 + g) << 1] + rs[((m0 + 8 + g) << 1) + 1]);

    // ---- normalize + store O ----
    float* o0 = out + ((size_t)(b * 1024 + q0 + m0 + g)) * 256;
    float* o1 = o0 + 2048;   // +8 rows
    #pragma unroll
    for (int dd = 0; dd < 8; dd++) {
        #pragma unroll
        for (int tt = 0; tt < 2; tt++) {
            int c0 = (dh << 7) + (dd << 4) + (tt << 3) + (tig << 1);
            float* a = &oacc[dd * 8 + tt * 4];
            float2 v0; v0.x = a[0] * inv0; v0.y = a[1] * inv0;
            float2 v1; v1.x = a[2] * inv1; v1.y = a[3] * inv1;
            *reinterpret_cast<float2*>(o0 + c0) = v0;
            *reinterpret_cast<float2*>(o1 + c0) = v1;
        }
    }
}

extern "C" void kernel_launch(void* const* d_in, const int* in_sizes, int n_in,
                              void* d_out, int out_size) {
    const float* q  = (const float*)d_in[0];
    const float* kv = (const float*)d_in[1];
    float* out = (float*)d_out;
    cudaFuncSetAttribute(attn_kernel, cudaFuncAttributeMaxDynamicSharedMemorySize, SMEM_BYTES);
    attn_kernel<<<512, 512, SMEM_BYTES>>>(q, kv, out);
}

// round 9
// speedup vs baseline: 1.2123x; 1.2123x over previous
#include <cuda_runtime.h>
#include <cuda_fp16.h>
#include <cstdint>
#include <cstddef>

// ---------------- SMEM layout (bytes) ----------------
// Q  : [128 rows][256 d] fp16, row stride 512B, 16B-chunk XOR swizzle -> 64KB
// KV : same layout -> 64KB (K operand for S, V operand (trans ldmatrix) for PV)
// P  : [128 rows][128 kv] fp16, row stride 256B, same swizzle -> 32KB
// RS : float[128][4] rowsum partials (one per kv-quarter warp)
#define SM_Q   0
#define SM_KV  65536
#define SM_P   131072
#define SM_RS  163840
#define SMEM_BYTES 165888

// ---------------- helpers ----------------
__device__ __forceinline__ uint32_t smem_u32(const void* p) {
    uint32_t a;
    asm("{ .reg .u64 t; cvta.to.shared.u64 t, %1; cvt.u32.u64 %0, t; }" : "=r"(a) : "l"(p));
    return a;
}
// pack two fp32 -> fp16x2, a in LOW half
__device__ __forceinline__ uint32_t f2h2(float a, float b) {
    uint32_t r;
    asm("cvt.rn.f16x2.f32 %0, %2, %1;" : "=r"(r) : "f"(a), "f"(b));
    return r;
}

#define STS32(addr, v) \
    asm volatile("st.shared.b32 [%0], %1;" :: "r"(addr), "r"(v) : "memory")
#define STS64(addr, v0, v1) \
    asm volatile("st.shared.v2.b32 [%0], {%1, %2};" :: "r"(addr), "r"(v0), "r"(v1) : "memory")

#define LDSM_X4(r0, r1, r2, r3, addr)                                          \
    asm volatile("ldmatrix.sync.aligned.m8n8.x4.shared.b16 {%0,%1,%2,%3}, [%4];" \
        : "=r"(r0), "=r"(r1), "=r"(r2), "=r"(r3) : "r"(addr))
#define LDSM_X4_T(r0, r1, r2, r3, addr)                                        \
    asm volatile("ldmatrix.sync.aligned.m8n8.x4.trans.shared.b16 {%0,%1,%2,%3}, [%4];" \
        : "=r"(r0), "=r"(r1), "=r"(r2), "=r"(r3) : "r"(addr))

// D(f32x4) += A(f16, m16k16) * B(f16, k16n8)
#define MMA(c, a0, a1, a2, a3, b0, b1)                                         \
    asm volatile("mma.sync.aligned.m16n8k16.row.col.f32.f16.f16.f32 "          \
        "{%0,%1,%2,%3},{%4,%5,%6,%7},{%8,%9},{%0,%1,%2,%3};"                   \
        : "+f"((c)[0]), "+f"((c)[1]), "+f"((c)[2]), "+f"((c)[3])               \
        : "r"(a0), "r"(a1), "r"(a2), "r"(a3), "r"(b0), "r"(b1))

// ---------------- kernel ----------------
// grid 512 = 64 batches x 8 q-tiles of 128 rows; block 512 = 16 warps.
// S  phase: warp w -> rows [32*(w>>2), +32), kv cols [32*(w&3), +32)   (m32 x n32)
// PV phase: warp w -> rows [32*(w>>2), +32), d  cols [64*(w&3), +64)   (m32 x n64)
__global__ void __launch_bounds__(512, 1)
attn_kernel(const float* __restrict__ q, const float* __restrict__ kv,
            float* __restrict__ out)
{
    extern __shared__ __align__(16) char smem[];
    const uint32_t sb = smem_u32(smem);
    const int tid  = threadIdx.x;
    const int lane = tid & 31, w = tid >> 5;
    const int b  = blockIdx.x >> 3;
    const int q0 = (blockIdx.x & 7) << 7;
    const int g = lane >> 2, tig = lane & 3;
    const int lj = lane & 7, sel = lane >> 3;
    const uint32_t swl = (uint32_t)lj << 4;
    const uint32_t gx  = (uint32_t)g << 4;

    const int m0  = (w >> 2) << 5;      // row base (both phases)
    const int n0s = (w & 3) << 5;       // S kv-quarter base
    const int d0q = (w & 3) << 6;       // PV d-quarter base

    // fragment lane geometry (validated in R8 kernel)
    const uint32_t colselA = (uint32_t)(sel >> 1) << 4;  // A-type and V-trans
    const uint32_t colselB = (uint32_t)(sel & 1) << 4;   // B-type non-trans
    const int rA = lj + ((sel & 1) << 3);
    const int rB = lj + ((sel >> 1) << 3);
    const int rV = lj + ((sel & 1) << 3);

    const uint32_t aQ0 = sb + SM_Q + (uint32_t)(m0 + rA) * 512u;
    const uint32_t aQ1 = aQ0 + 16u * 512u;
    const uint32_t aP0 = sb + SM_P + (uint32_t)(m0 + rA) * 256u;
    const uint32_t aP1 = aP0 + 16u * 256u;
    const uint32_t bK0 = sb + SM_KV + (uint32_t)(n0s + rB) * 512u;
    const uint32_t bK1 = bK0 + 16u * 512u;

    // P store bases: mb=0 rows (m0+g, m0+8+g); mb=1 adds 16 rows (4096B)
    const uint32_t pr0 = sb + SM_P + (uint32_t)(m0 + g) * 256u;

    // ---- load Q tile (scale 1/16 folded), fp32 -> fp16, swizzled ----
    {
        const float4* gq = reinterpret_cast<const float4*>(q + ((size_t)(b * 1024 + q0)) * 256);
        #pragma unroll
        for (int i = 0; i < 16; i++) {
            int idx = tid + (i << 9);
            float4 v = gq[idx];
            int r = idx >> 6;
            uint32_t c2 = (uint32_t)(idx & 63) << 3;
            uint32_t ad = sb + SM_Q + (uint32_t)r * 512u + (c2 ^ ((uint32_t)(r & 7) << 4));
            STS64(ad, f2h2(v.x * 0.0625f, v.y * 0.0625f), f2h2(v.z * 0.0625f, v.w * 0.0625f));
        }
    }

    float oacc[64];                      // [mb*32 + dd*8 + tt*4 + i]
    #pragma unroll
    for (int i = 0; i < 64; i++) oacc[i] = 0.f;
    float rsum[4] = {0.f, 0.f, 0.f, 0.f};  // [mb*2 + h]: rows m0+mb*16+g+h*8

    const float4* gkv = reinterpret_cast<const float4*>(kv + (size_t)b * 262144);

    for (int t = 0; t < 8; t++) {
        __syncthreads();                 // prev PV done reading KV & P
        // ---- load KV tile t ----
        #pragma unroll
        for (int i = 0; i < 16; i++) {
            int idx = tid + (i << 9);
            float4 v = gkv[(t << 13) + idx];
            int r = idx >> 6;
            uint32_t c2 = (uint32_t)(idx & 63) << 3;
            uint32_t ad = sb + SM_KV + (uint32_t)r * 512u + (c2 ^ ((uint32_t)(r & 7) << 4));
            STS64(ad, f2h2(v.x, v.y), f2h2(v.z, v.w));
        }
        __syncthreads();

        // ---- S = Qs . K^T  (m32 x n32, k256) ----
        float sacc[32];                  // [mb*16 + nb*8 + tt*4 + i]
        #pragma unroll
        for (int i = 0; i < 32; i++) sacc[i] = 0.f;
        #pragma unroll
        for (int kk = 0; kk < 16; kk++) {
            const uint32_t ka = (((uint32_t)kk << 5) | colselA) ^ swl;
            const uint32_t kb = (((uint32_t)kk << 5) | colselB) ^ swl;
            uint32_t a0, a1, a2, a3, a4, a5, a6, a7;
            LDSM_X4(a0, a1, a2, a3, aQ0 + ka);
            LDSM_X4(a4, a5, a6, a7, aQ1 + ka);
            #pragma unroll
            for (int nb = 0; nb < 2; nb++) {
                uint32_t b0, b1, b2, b3;
                LDSM_X4(b0, b1, b2, b3, (nb ? bK1 : bK0) + kb);
                MMA(&sacc[nb * 8 + 0],      a0, a1, a2, a3, b0, b1);
                MMA(&sacc[nb * 8 + 4],      a0, a1, a2, a3, b2, b3);
                MMA(&sacc[16 + nb * 8 + 0], a4, a5, a6, a7, b0, b1);
                MMA(&sacc[16 + nb * 8 + 4], a4, a5, a6, a7, b2, b3);
            }
        }

        // ---- P = exp(S) -> smem; accumulate rowsums ----
        #pragma unroll
        for (int mb = 0; mb < 2; mb++) {
            const uint32_t base = pr0 + (uint32_t)(mb << 12);   // +16 rows = 4096B
            #pragma unroll
            for (int j = 0; j < 4; j++) {                        // j = nb*2 + tt
                float* c = &sacc[mb * 16 + j * 4];
                float e0 = __expf(c[0]), e1 = __expf(c[1]);
                float e2 = __expf(c[2]), e3 = __expf(c[3]);
                rsum[mb * 2]     += e0 + e1;
                rsum[mb * 2 + 1] += e2 + e3;
                uint32_t col2 = ((uint32_t)(n0s + (j << 3) + (tig << 1)) << 1);
                STS32(base + (col2 ^ gx),         f2h2(e0, e1));
                STS32(base + 2048u + (col2 ^ gx), f2h2(e2, e3));
            }
        }
        __syncthreads();                 // P fully exchanged

        // ---- O += P . V  (m32 x n64, k128) ----
        #pragma unroll
        for (int kk = 0; kk < 8; kk++) {
            const uint32_t ka = (((uint32_t)kk << 5) | colselA) ^ swl;
            uint32_t a0, a1, a2, a3, a4, a5, a6, a7;
            LDSM_X4(a0, a1, a2, a3, aP0 + ka);
            LDSM_X4(a4, a5, a6, a7, aP1 + ka);
            const uint32_t vrow = sb + SM_KV + (uint32_t)((kk << 4) + rV) * 512u;
            #pragma unroll
            for (int dd = 0; dd < 4; dd++) {
                uint32_t b0, b1, b2, b3;
                uint32_t va = vrow + ((((uint32_t)(d0q + (dd << 4)) << 1) | colselA) ^ swl);
                LDSM_X4_T(b0, b1, b2, b3, va);
                MMA(&oacc[dd * 8 + 0],      a0, a1, a2, a3, b0, b1);
                MMA(&oacc[dd * 8 + 4],      a0, a1, a2, a3, b2, b3);
                MMA(&oacc[32 + dd * 8 + 0], a4, a5, a6, a7, b0, b1);
                MMA(&oacc[32 + dd * 8 + 4], a4, a5, a6, a7, b2, b3);
            }
        }
    }

    // ---- rowsums: quad-reduce, combine 4 kv-quarters via smem ----
    #pragma unroll
    for (int i = 0; i < 4; i++) {
        rsum[i] += __shfl_xor_sync(0xffffffffu, rsum[i], 1);
        rsum[i] += __shfl_xor_sync(0xffffffffu, rsum[i], 2);
    }
    float* rs = reinterpret_cast<float*>(smem + SM_RS);   // [128][4]
    if (tig == 0) {
        rs[((m0 + g) << 2)      + (w & 3)] = rsum[0];
        rs[((m0 + 8 + g) << 2)  + (w & 3)] = rsum[1];
        rs[((m0 + 16 + g) << 2) + (w & 3)] = rsum[2];
        rs[((m0 + 24 + g) << 2) + (w & 3)] = rsum[3];
    }
    __syncthreads();

    // ---- normalize + store O ----
    #pragma unroll
    for (int mb = 0; mb < 2; mb++) {
        const int r0 = m0 + (mb << 4) + g;
        const float inv0 = 1.0f / (rs[(r0 << 2)] + rs[(r0 << 2) + 1] +
                                   rs[(r0 << 2) + 2] + rs[(r0 << 2) + 3]);
        const int r1 = r0 + 8;
        const float inv1 = 1.0f / (rs[(r1 << 2)] + rs[(r1 << 2) + 1] +
                                   rs[(r1 << 2) + 2] + rs[(r1 << 2) + 3]);
        float* o0 = out + ((size_t)(b * 1024 + q0 + r0)) * 256;
        float* o1 = o0 + 2048;           // +8 rows
        #pragma unroll
        for (int dd = 0; dd < 4; dd++) {
            #pragma unroll
            for (int tt = 0; tt < 2; tt++) {
                float* c = &oacc[mb * 32 + dd * 8 + tt * 4];
                int col = d0q + (dd << 4) + (tt << 3) + (tig << 1);
                float2 v0; v0.x = c[0] * inv0; v0.y = c[1] * inv0;
                float2 v1; v1.x = c[2] * inv1; v1.y = c[3] * inv1;
                *reinterpret_cast<float2*>(o0 + col) = v0;
                *reinterpret_cast<float2*>(o1 + col) = v1;
            }
        }
    }
}

extern "C" void kernel_launch(void* const* d_in, const int* in_sizes, int n_in,
                              void* d_out, int out_size) {
    const float* q  = (const float*)d_in[0];
    const float* kv = (const float*)d_in[1];
    float* out = (float*)d_out;
    cudaFuncSetAttribute(attn_kernel, cudaFuncAttributeMaxDynamicSharedMemorySize, SMEM_BYTES);
    attn_kernel<<<512, 512, SMEM_BYTES>>>(q, kv, out);
}